// round 1
// baseline (speedup 1.0000x reference)
#include <cuda_runtime.h>
#include <cuda_bf16.h>
#include <math.h>

// Problem constants
#define BB 2
#define SS 2048
#define DD 768
#define NH 12
#define DK 64
#define DV 64
#define GG 1
#define NIDX 6
#define SMID (SS - 2*GG)          // 2046 middle rows
#define MROWS (BB * SS)           // 4096

// Scratch (static device globals; allocation in kernel_launch is forbidden)
__device__ float g_q[MROWS * DD];
__device__ float g_k[MROWS * DD];
__device__ float g_v[MROWS * DD];
__device__ float g_attn[MROWS * DD];
__device__ float g_vsum[BB * NH * DV];

// ---------------------------------------------------------------------------
// SGEMM: C[M,N] = A[M,K] * W[N,K]^T   (all row-major, M%128==0, N%128==0, K%8==0)
// 128x128 block tile, 8x8 thread tile, BK=8, 256 threads.
// ---------------------------------------------------------------------------
#define BM 128
#define BN 128
#define BK 8

__global__ __launch_bounds__(256, 2) void sgemm_abt(
    const float* __restrict__ A, const float* __restrict__ W,
    float* __restrict__ C, int M, int N, int K)
{
    __shared__ float As[BK][BM + 4];
    __shared__ float Ws[BK][BN + 4];

    const int tid = threadIdx.x;
    const int tx = tid % 16;          // N direction
    const int ty = tid / 16;          // M direction
    const int bm = blockIdx.y * BM;
    const int bn = blockIdx.x * BN;

    // Each thread loads one float4 of A and one float4 of W per k-tile.
    const int lrow = tid >> 1;            // 0..127
    const int lk4  = (tid & 1) * 4;       // 0 or 4

    float acc[8][8];
    #pragma unroll
    for (int i = 0; i < 8; i++)
        #pragma unroll
        for (int j = 0; j < 8; j++) acc[i][j] = 0.0f;

    for (int k0 = 0; k0 < K; k0 += BK) {
        float4 a4 = *reinterpret_cast<const float4*>(A + (size_t)(bm + lrow) * K + k0 + lk4);
        float4 w4 = *reinterpret_cast<const float4*>(W + (size_t)(bn + lrow) * K + k0 + lk4);
        As[lk4 + 0][lrow] = a4.x; As[lk4 + 1][lrow] = a4.y;
        As[lk4 + 2][lrow] = a4.z; As[lk4 + 3][lrow] = a4.w;
        Ws[lk4 + 0][lrow] = w4.x; Ws[lk4 + 1][lrow] = w4.y;
        Ws[lk4 + 2][lrow] = w4.z; Ws[lk4 + 3][lrow] = w4.w;
        __syncthreads();

        #pragma unroll
        for (int kk = 0; kk < BK; kk++) {
            float ar[8], wr[8];
            #pragma unroll
            for (int i = 0; i < 8; i++) ar[i] = As[kk][ty * 8 + i];
            #pragma unroll
            for (int j = 0; j < 8; j++) wr[j] = Ws[kk][tx * 8 + j];
            #pragma unroll
            for (int i = 0; i < 8; i++)
                #pragma unroll
                for (int j = 0; j < 8; j++)
                    acc[i][j] = fmaf(ar[i], wr[j], acc[i][j]);
        }
        __syncthreads();
    }

    #pragma unroll
    for (int i = 0; i < 8; i++) {
        float* crow = C + (size_t)(bm + ty * 8 + i) * N + bn + tx * 8;
        #pragma unroll
        for (int j = 0; j < 8; j += 4) {
            float4 o = make_float4(acc[i][j], acc[i][j+1], acc[i][j+2], acc[i][j+3]);
            *reinterpret_cast<float4*>(crow + j) = o;
        }
    }
}

// ---------------------------------------------------------------------------
// Vsum[b,h,dv] = sum_s v[b,s,h*64+dv]
// grid: BB*NH blocks, 256 threads
// ---------------------------------------------------------------------------
__global__ void vsum_kernel()
{
    int bh = blockIdx.x;
    int b = bh / NH, h = bh % NH;
    int dv = threadIdx.x % DV;
    int chunk = threadIdx.x / DV;   // 0..3
    const float* vb = g_v + (size_t)b * SS * DD + h * DV;
    float acc = 0.0f;
    for (int s = chunk * (SS/4); s < (chunk + 1) * (SS/4); s++)
        acc += vb[(size_t)s * DD + dv];
    __shared__ float red[256];
    red[threadIdx.x] = acc;
    __syncthreads();
    if (threadIdx.x < DV)
        g_vsum[bh * DV + dv] = red[dv] + red[DV + dv] + red[2*DV + dv] + red[3*DV + dv];
}

// ---------------------------------------------------------------------------
// Middle rows: one warp per (b,h,i). out = (Vsum + sum_u (e_j-1) v_j) / (S + sum_u (e_j-1))
// ---------------------------------------------------------------------------
__global__ void mid_kernel(const int* __restrict__ idx)
{
    const int warps_per_block = 8;
    int item = blockIdx.x * warps_per_block + (threadIdx.x >> 5);
    const int n_items = BB * NH * SMID;
    if (item >= n_items) return;
    int lane = threadIdx.x & 31;

    int i = item % SMID;
    int h = (item / SMID) % NH;
    int b = item / (SMID * NH);
    int s = i + GG;

    const float* qrow = g_q + ((size_t)b * SS + s) * DD + h * DK;
    float q0 = qrow[lane];
    float q1 = qrow[lane + 32];

    int cols[NIDX];
    #pragma unroll
    for (int j = 0; j < NIDX; j++) cols[j] = idx[i * NIDX + j];

    float sc[NIDX];
    #pragma unroll
    for (int j = 0; j < NIDX; j++) {
        const float* krow = g_k + ((size_t)b * SS + cols[j]) * DD + h * DK;
        float p = q0 * krow[lane] + q1 * krow[lane + 32];
        #pragma unroll
        for (int o = 16; o > 0; o >>= 1) p += __shfl_xor_sync(0xFFFFFFFFu, p, o);
        sc[j] = p;
    }

    // dedupe (duplicate columns carry identical scores -> skip repeats) + exp
    float wgt[NIDX];
    float denom = (float)SS;
    #pragma unroll
    for (int j = 0; j < NIDX; j++) {
        bool dup = false;
        #pragma unroll
        for (int jj = 0; jj < NIDX; jj++)
            if (jj < j) dup = dup || (cols[jj] == cols[j]);
        float w = dup ? 0.0f : (expf(sc[j] * 0.125f) - 1.0f);
        wgt[j] = w;
        denom += w;
    }

    const float* vs = g_vsum + (b * NH + h) * DV;
    float o0 = vs[lane];
    float o1 = vs[lane + 32];
    #pragma unroll
    for (int j = 0; j < NIDX; j++) {
        const float* vrow = g_v + ((size_t)b * SS + cols[j]) * DD + h * DV;
        o0 = fmaf(wgt[j], vrow[lane], o0);
        o1 = fmaf(wgt[j], vrow[lane + 32], o1);
    }
    float inv = 1.0f / denom;
    float* orow = g_attn + ((size_t)b * SS + s) * DD + h * DV;
    orow[lane] = o0 * inv;
    orow[lane + 32] = o1 * inv;
}

// ---------------------------------------------------------------------------
// Global rows (s=0 and s=2047): full softmax attention over all 2048 keys.
// grid: BB*NH*2 = 48 blocks, 256 threads
// ---------------------------------------------------------------------------
__global__ void global_kernel()
{
    int item = blockIdx.x;
    int r = item % 2;
    int h = (item / 2) % NH;
    int b = item / (2 * NH);
    int s = r ? (SS - 1) : 0;
    int tid = threadIdx.x;

    __shared__ float sc[SS];
    __shared__ float qs[DK];
    __shared__ float red[256];

    const float* qrow = g_q + ((size_t)b * SS + s) * DD + h * DK;
    if (tid < DK) qs[tid] = qrow[tid];
    __syncthreads();

    for (int t = tid; t < SS; t += 256) {
        const float* krow = g_k + ((size_t)b * SS + t) * DD + h * DK;
        float p = 0.0f;
        #pragma unroll
        for (int d = 0; d < DK; d++) p = fmaf(qs[d], krow[d], p);
        sc[t] = p * 0.125f;
    }
    __syncthreads();

    // row max
    float m = -1e30f;
    for (int t = tid; t < SS; t += 256) m = fmaxf(m, sc[t]);
    red[tid] = m; __syncthreads();
    for (int o = 128; o > 0; o >>= 1) {
        if (tid < o) red[tid] = fmaxf(red[tid], red[tid + o]);
        __syncthreads();
    }
    m = red[0];
    __syncthreads();

    // exp + sum
    float sum = 0.0f;
    for (int t = tid; t < SS; t += 256) {
        float e = expf(sc[t] - m);
        sc[t] = e;
        sum += e;
    }
    red[tid] = sum; __syncthreads();
    for (int o = 128; o > 0; o >>= 1) {
        if (tid < o) red[tid] += red[tid + o];
        __syncthreads();
    }
    float inv = 1.0f / red[0];
    __syncthreads();

    // weighted sum of V
    int dv = tid % DV;
    int chunk = tid / DV;  // 0..3
    float acc = 0.0f;
    const float* vb = g_v + (size_t)b * SS * DD + h * DV + dv;
    for (int t = chunk * (SS/4); t < (chunk + 1) * (SS/4); t++)
        acc = fmaf(sc[t], vb[(size_t)t * DD], acc);
    red[tid] = acc; __syncthreads();
    if (tid < DV) {
        float o = (red[dv] + red[DV + dv] + red[2*DV + dv] + red[3*DV + dv]) * inv;
        g_attn[((size_t)b * SS + s) * DD + h * DV + dv] = o;
    }
}

// ---------------------------------------------------------------------------
extern "C" void kernel_launch(void* const* d_in, const int* in_sizes, int n_in,
                              void* d_out, int out_size)
{
    const float* Q  = (const float*)d_in[0];
    const float* K  = (const float*)d_in[1];
    const float* V  = (const float*)d_in[2];
    const float* Wq = (const float*)d_in[3];
    const float* Wk = (const float*)d_in[4];
    const float* Wv = (const float*)d_in[5];
    const float* Wo = (const float*)d_in[6];
    const int*   idx = (const int*)d_in[7];
    float* out = (float*)d_out;

    float *pq, *pk, *pv, *pa;
    cudaGetSymbolAddress((void**)&pq, g_q);
    cudaGetSymbolAddress((void**)&pk, g_k);
    cudaGetSymbolAddress((void**)&pv, g_v);
    cudaGetSymbolAddress((void**)&pa, g_attn);

    dim3 gg(DD / BN, MROWS / BM);   // (6, 32)

    sgemm_abt<<<gg, 256>>>(Q, Wq, pq, MROWS, DD, DD);
    sgemm_abt<<<gg, 256>>>(K, Wk, pk, MROWS, DD, DD);
    sgemm_abt<<<gg, 256>>>(V, Wv, pv, MROWS, DD, DD);

    vsum_kernel<<<BB * NH, 256>>>();

    const int n_items = BB * NH * SMID;                 // 49104
    mid_kernel<<<(n_items + 7) / 8, 256>>>(idx);

    global_kernel<<<BB * NH * 2, 256>>>();

    sgemm_abt<<<gg, 256>>>(pa, Wo, out, MROWS, DD, DD);
}

// round 3
// speedup vs baseline: 2.0318x; 2.0318x over previous
#include <cuda_runtime.h>
#include <cuda_bf16.h>
#include <cstdint>
#include <math.h>

// Problem constants
#define BB 2
#define SS 2048
#define DD 768
#define NH 12
#define DK 64
#define DV 64
#define GG 1
#define NIDX 6
#define SMID (SS - 2*GG)          // 2046 middle rows
#define MROWS (BB * SS)           // 4096

// GEMM tiling
#define BM 128
#define BN 128
#define BKK 32                    // bf16 K elems per stage
#define NCHK (DD / BKK)           // 24 k-iterations
#define LDT 40                    // padded row stride (elements): 80B, conflict-free
#define TILEB (128 * LDT * 2)     // 10240 B per tile
#define STAGEB (4 * TILEB)        // Ah, Al, Bh, Bl
#define GSMEM (2 * STAGEB)        // 81920 B double-buffered

// ---------------------------------------------------------------------------
// Scratch (static device globals; runtime allocation is forbidden)
// ---------------------------------------------------------------------------
__device__ float g_q[MROWS * DD];
__device__ float g_k[MROWS * DD];
__device__ float g_v[MROWS * DD];
__device__ float g_attn[MROWS * DD];
__device__ float g_vsum[BB * NH * DV];

__device__ __nv_bfloat16 g_qh[MROWS * DD], g_ql[MROWS * DD];
__device__ __nv_bfloat16 g_kh[MROWS * DD], g_kl[MROWS * DD];
__device__ __nv_bfloat16 g_vh[MROWS * DD], g_vl[MROWS * DD];
__device__ __nv_bfloat16 g_ah[MROWS * DD], g_al[MROWS * DD];
__device__ __nv_bfloat16 g_wqh[DD * DD], g_wql[DD * DD];
__device__ __nv_bfloat16 g_wkh[DD * DD], g_wkl[DD * DD];
__device__ __nv_bfloat16 g_wvh[DD * DD], g_wvl[DD * DD];
__device__ __nv_bfloat16 g_woh[DD * DD], g_wol[DD * DD];

// ---------------------------------------------------------------------------
// PTX helpers (portable: sm_80+ baseline ISA, compiles for compute_103)
// ---------------------------------------------------------------------------
__device__ __forceinline__ uint32_t smem_u32(const void* p) {
    uint32_t a;
    asm("{ .reg .u64 t; cvta.to.shared.u64 t, %1; cvt.u32.u64 %0, t; }"
        : "=r"(a) : "l"(p));
    return a;
}

__device__ __forceinline__ void cp_async16(uint32_t dst, const void* src) {
    asm volatile("cp.async.cg.shared.global [%0], [%1], 16;"
                 :: "r"(dst), "l"(src) : "memory");
}
__device__ __forceinline__ void cp_commit() {
    asm volatile("cp.async.commit_group;" ::: "memory");
}
template <int N>
__device__ __forceinline__ void cp_wait() {
    asm volatile("cp.async.wait_group %0;" :: "n"(N) : "memory");
}

__device__ __forceinline__ void ldm4(uint32_t* r, uint32_t addr) {
    asm volatile("ldmatrix.sync.aligned.m8n8.x4.shared.b16 {%0,%1,%2,%3}, [%4];"
                 : "=r"(r[0]), "=r"(r[1]), "=r"(r[2]), "=r"(r[3]) : "r"(addr));
}

__device__ __forceinline__ void mma16816(float* c, const uint32_t* a, const uint32_t* b) {
    asm volatile(
        "mma.sync.aligned.m16n8k16.row.col.f32.bf16.bf16.f32 "
        "{%0,%1,%2,%3}, {%4,%5,%6,%7}, {%8,%9}, {%0,%1,%2,%3};"
        : "+f"(c[0]), "+f"(c[1]), "+f"(c[2]), "+f"(c[3])
        : "r"(a[0]), "r"(a[1]), "r"(a[2]), "r"(a[3]), "r"(b[0]), "r"(b[1]));
}

// ---------------------------------------------------------------------------
// C[M,768] = Ah*Bh^T + Ah*Bl^T + Al*Bh^T  (bf16 split-fp32), B is [768,768]
// 128x128 CTA tile, 8 warps (2m x 4n), 64x32 warp tile, BK=32, cp.async x2.
// ---------------------------------------------------------------------------
__global__ __launch_bounds__(256, 1) void gemm_mma(
    const __nv_bfloat16* __restrict__ Ah, const __nv_bfloat16* __restrict__ Al,
    const __nv_bfloat16* __restrict__ Bh, const __nv_bfloat16* __restrict__ Bl,
    float* __restrict__ C)
{
    extern __shared__ char smem[];
    const uint32_t sb = smem_u32(smem);
    const int tid = threadIdx.x;
    const int wid = tid >> 5;
    const int lane = tid & 31;
    const int bm = blockIdx.y * BM;
    const int bn = blockIdx.x * BN;
    const int wm = (wid >> 2) * 64;     // warp m offset in CTA tile
    const int wn = (wid & 3) * 32;      // warp n offset in CTA tile

    float acc[4][4][4];
    #pragma unroll
    for (int i = 0; i < 4; i++)
        #pragma unroll
        for (int j = 0; j < 4; j++)
            #pragma unroll
            for (int e = 0; e < 4; e++) acc[i][j][e] = 0.0f;

    const __nv_bfloat16* srcs[4] = {Ah, Al, Bh, Bl};
    const int rows0[4] = {bm, bm, bn, bn};

    // issue cp.async for k-chunk kt into stage st
    auto issue = [&](int kt, int st) {
        #pragma unroll
        for (int q8 = 0; q8 < 8; q8++) {
            int q = tid + q8 * 256;            // 0..2047
            int t = q >> 9;                    // which tile
            int r = (q >> 2) & 127;            // row
            int c = q & 3;                     // 16B chunk within row
            const __nv_bfloat16* src = srcs[t] + (size_t)(rows0[t] + r) * DD
                                       + kt * BKK + c * 8;
            uint32_t dst = sb + st * STAGEB + t * TILEB + r * (LDT * 2) + c * 16;
            cp_async16(dst, src);
        }
        cp_commit();
    };

    // fragment address components
    const int a_row = lane & 15;              // m within 16
    const int a_col = (lane >> 4) * 8;        // k within 16
    const int b_row = (lane & 7) + ((lane >> 4) << 3);   // n within 16
    const int b_col = ((lane >> 3) & 1) * 8;             // k within 16

    auto compute = [&](int st) {
        const uint32_t base = sb + st * STAGEB;
        #pragma unroll
        for (int ks = 0; ks < 2; ks++) {
            const int k0 = ks * 16;
            uint32_t ah[4][4], al[4][4];
            #pragma unroll
            for (int mt = 0; mt < 4; mt++) {
                uint32_t off = (uint32_t)(wm + mt * 16 + a_row) * (LDT * 2)
                             + (k0 + a_col) * 2;
                ldm4(ah[mt], base + off);
                ldm4(al[mt], base + TILEB + off);
            }
            uint32_t bh[2][4], bl[2][4];
            #pragma unroll
            for (int nh = 0; nh < 2; nh++) {
                uint32_t off = (uint32_t)(wn + nh * 16 + b_row) * (LDT * 2)
                             + (k0 + b_col) * 2;
                ldm4(bh[nh], base + 2 * TILEB + off);
                ldm4(bl[nh], base + 3 * TILEB + off);
            }
            #pragma unroll
            for (int mt = 0; mt < 4; mt++)
                #pragma unroll
                for (int j = 0; j < 4; j++) {
                    const uint32_t* bhp = &bh[j >> 1][(j & 1) * 2];
                    const uint32_t* blp = &bl[j >> 1][(j & 1) * 2];
                    mma16816(acc[mt][j], ah[mt], bhp);
                    mma16816(acc[mt][j], ah[mt], blp);
                    mma16816(acc[mt][j], al[mt], bhp);
                }
        }
    };

    issue(0, 0);
    for (int kt = 0; kt < NCHK; kt++) {
        if (kt + 1 < NCHK) {
            issue(kt + 1, (kt + 1) & 1);
            cp_wait<1>();
        } else {
            cp_wait<0>();
        }
        __syncthreads();
        compute(kt & 1);
        __syncthreads();
    }

    // epilogue: fp32 fragment -> global
    #pragma unroll
    for (int mt = 0; mt < 4; mt++) {
        #pragma unroll
        for (int j = 0; j < 4; j++) {
            int row = bm + wm + mt * 16 + (lane >> 2);
            int col = bn + wn + j * 8 + (lane & 3) * 2;
            *reinterpret_cast<float2*>(C + (size_t)row * DD + col)
                = make_float2(acc[mt][j][0], acc[mt][j][1]);
            *reinterpret_cast<float2*>(C + (size_t)(row + 8) * DD + col)
                = make_float2(acc[mt][j][2], acc[mt][j][3]);
        }
    }
}

// ---------------------------------------------------------------------------
// fp32 -> (bf16 hi, bf16 lo) split, vectorized x4
// ---------------------------------------------------------------------------
__global__ void split_bf16(const float4* __restrict__ x,
                           ushort4* __restrict__ hi, ushort4* __restrict__ lo,
                           int n4)
{
    int i = blockIdx.x * blockDim.x + threadIdx.x;
    if (i >= n4) return;
    float4 v = x[i];
    ushort4 h, l;
    __nv_bfloat16 b;
    b = __float2bfloat16(v.x); h.x = __bfloat16_as_ushort(b);
    l.x = __bfloat16_as_ushort(__float2bfloat16(v.x - __bfloat162float(b)));
    b = __float2bfloat16(v.y); h.y = __bfloat16_as_ushort(b);
    l.y = __bfloat16_as_ushort(__float2bfloat16(v.y - __bfloat162float(b)));
    b = __float2bfloat16(v.z); h.z = __bfloat16_as_ushort(b);
    l.z = __bfloat16_as_ushort(__float2bfloat16(v.z - __bfloat162float(b)));
    b = __float2bfloat16(v.w); h.w = __bfloat16_as_ushort(b);
    l.w = __bfloat16_as_ushort(__float2bfloat16(v.w - __bfloat162float(b)));
    hi[i] = h; lo[i] = l;
}

// ---------------------------------------------------------------------------
// Vsum[b,h,dv] = sum_s v[b,s,h*64+dv]
// ---------------------------------------------------------------------------
__global__ void zero_vsum() {
    int i = blockIdx.x * blockDim.x + threadIdx.x;
    if (i < BB * NH * DV) g_vsum[i] = 0.0f;
}

__global__ void vsum_kernel() {
    int bh = blockIdx.x;               // 0..23
    int chunk = blockIdx.y;            // 0..7
    int b = bh / NH, h = bh % NH;
    int dv = threadIdx.x & 63;
    int sub = threadIdx.x >> 6;        // 0..3
    const float* vb = g_v + (size_t)b * SS * DD + h * DV;
    int s0 = chunk * (SS / 8) + sub * (SS / 32);
    float acc = 0.0f;
    for (int s = s0; s < s0 + SS / 32; s++)
        acc += vb[(size_t)s * DD + dv];
    __shared__ float red[256];
    red[threadIdx.x] = acc;
    __syncthreads();
    if (threadIdx.x < DV)
        atomicAdd(&g_vsum[bh * DV + dv],
                  red[dv] + red[64 + dv] + red[128 + dv] + red[192 + dv]);
}

// ---------------------------------------------------------------------------
// Middle rows: out = (Vsum + sum_uniq (e_j-1) v_j) / (S + sum_uniq (e_j-1))
// ---------------------------------------------------------------------------
__global__ void mid_kernel(const int* __restrict__ idx)
{
    const int warps_per_block = 8;
    int item = blockIdx.x * warps_per_block + (threadIdx.x >> 5);
    const int n_items = BB * NH * SMID;
    if (item >= n_items) return;
    int lane = threadIdx.x & 31;

    int i = item % SMID;
    int h = (item / SMID) % NH;
    int b = item / (SMID * NH);
    int s = i + GG;

    const float* qrow = g_q + ((size_t)b * SS + s) * DD + h * DK;
    float q0 = qrow[lane];
    float q1 = qrow[lane + 32];

    int cols[NIDX];
    #pragma unroll
    for (int j = 0; j < NIDX; j++) cols[j] = idx[i * NIDX + j];

    float sc[NIDX];
    #pragma unroll
    for (int j = 0; j < NIDX; j++) {
        const float* krow = g_k + ((size_t)b * SS + cols[j]) * DD + h * DK;
        float p = q0 * krow[lane] + q1 * krow[lane + 32];
        #pragma unroll
        for (int o = 16; o > 0; o >>= 1) p += __shfl_xor_sync(0xFFFFFFFFu, p, o);
        sc[j] = p;
    }

    float wgt[NIDX];
    float denom = (float)SS;
    #pragma unroll
    for (int j = 0; j < NIDX; j++) {
        bool dup = false;
        #pragma unroll
        for (int jj = 0; jj < NIDX; jj++)
            if (jj < j) dup = dup || (cols[jj] == cols[j]);
        float w = dup ? 0.0f : (expf(sc[j] * 0.125f) - 1.0f);
        wgt[j] = w;
        denom += w;
    }

    const float* vs = g_vsum + (b * NH + h) * DV;
    float o0 = vs[lane];
    float o1 = vs[lane + 32];
    #pragma unroll
    for (int j = 0; j < NIDX; j++) {
        const float* vrow = g_v + ((size_t)b * SS + cols[j]) * DD + h * DV;
        o0 = fmaf(wgt[j], vrow[lane], o0);
        o1 = fmaf(wgt[j], vrow[lane + 32], o1);
    }
    float inv = 1.0f / denom;
    float* orow = g_attn + ((size_t)b * SS + s) * DD + h * DV;
    orow[lane] = o0 * inv;
    orow[lane + 32] = o1 * inv;
}

// ---------------------------------------------------------------------------
// Global rows (s=0, s=2047): full softmax over all 2048 keys.
// ---------------------------------------------------------------------------
__global__ void global_kernel()
{
    int item = blockIdx.x;
    int r = item % 2;
    int h = (item / 2) % NH;
    int b = item / (2 * NH);
    int s = r ? (SS - 1) : 0;
    int tid = threadIdx.x;

    __shared__ float sc[SS];
    __shared__ float qs[DK];
    __shared__ float red[256];

    const float* qrow = g_q + ((size_t)b * SS + s) * DD + h * DK;
    if (tid < DK) qs[tid] = qrow[tid];
    __syncthreads();

    for (int t = tid; t < SS; t += 256) {
        const float* krow = g_k + ((size_t)b * SS + t) * DD + h * DK;
        float p = 0.0f;
        #pragma unroll
        for (int d = 0; d < DK; d++) p = fmaf(qs[d], krow[d], p);
        sc[t] = p * 0.125f;
    }
    __syncthreads();

    float m = -1e30f;
    for (int t = tid; t < SS; t += 256) m = fmaxf(m, sc[t]);
    red[tid] = m; __syncthreads();
    for (int o = 128; o > 0; o >>= 1) {
        if (tid < o) red[tid] = fmaxf(red[tid], red[tid + o]);
        __syncthreads();
    }
    m = red[0];
    __syncthreads();

    float sum = 0.0f;
    for (int t = tid; t < SS; t += 256) {
        float e = expf(sc[t] - m);
        sc[t] = e;
        sum += e;
    }
    red[tid] = sum; __syncthreads();
    for (int o = 128; o > 0; o >>= 1) {
        if (tid < o) red[tid] += red[tid + o];
        __syncthreads();
    }
    float inv = 1.0f / red[0];
    __syncthreads();

    int dv = tid % DV;
    int chunk = tid / DV;
    float acc = 0.0f;
    const float* vb = g_v + (size_t)b * SS * DD + h * DV + dv;
    for (int t = chunk * (SS / 4); t < (chunk + 1) * (SS / 4); t++)
        acc = fmaf(sc[t], vb[(size_t)t * DD], acc);
    red[tid] = acc; __syncthreads();
    if (tid < DV) {
        float o = (red[dv] + red[DV + dv] + red[2 * DV + dv] + red[3 * DV + dv]) * inv;
        g_attn[((size_t)b * SS + s) * DD + h * DV + dv] = o;
    }
}

// ---------------------------------------------------------------------------
extern "C" void kernel_launch(void* const* d_in, const int* in_sizes, int n_in,
                              void* d_out, int out_size)
{
    const float* Q  = (const float*)d_in[0];
    const float* K  = (const float*)d_in[1];
    const float* V  = (const float*)d_in[2];
    const float* Wq = (const float*)d_in[3];
    const float* Wk = (const float*)d_in[4];
    const float* Wv = (const float*)d_in[5];
    const float* Wo = (const float*)d_in[6];
    const int*   idx = (const int*)d_in[7];
    float* out = (float*)d_out;

    float *pq, *pk, *pv, *pa;
    cudaGetSymbolAddress((void**)&pq, g_q);
    cudaGetSymbolAddress((void**)&pk, g_k);
    cudaGetSymbolAddress((void**)&pv, g_v);
    cudaGetSymbolAddress((void**)&pa, g_attn);

    __nv_bfloat16 *qh, *ql, *kh, *kl, *vh, *vl, *ah, *al;
    __nv_bfloat16 *wqh, *wql, *wkh, *wkl, *wvh, *wvl, *woh, *wol;
    cudaGetSymbolAddress((void**)&qh, g_qh);  cudaGetSymbolAddress((void**)&ql, g_ql);
    cudaGetSymbolAddress((void**)&kh, g_kh);  cudaGetSymbolAddress((void**)&kl, g_kl);
    cudaGetSymbolAddress((void**)&vh, g_vh);  cudaGetSymbolAddress((void**)&vl, g_vl);
    cudaGetSymbolAddress((void**)&ah, g_ah);  cudaGetSymbolAddress((void**)&al, g_al);
    cudaGetSymbolAddress((void**)&wqh, g_wqh); cudaGetSymbolAddress((void**)&wql, g_wql);
    cudaGetSymbolAddress((void**)&wkh, g_wkh); cudaGetSymbolAddress((void**)&wkl, g_wkl);
    cudaGetSymbolAddress((void**)&wvh, g_wvh); cudaGetSymbolAddress((void**)&wvl, g_wvl);
    cudaGetSymbolAddress((void**)&woh, g_woh); cudaGetSymbolAddress((void**)&wol, g_wol);

    cudaFuncSetAttribute(gemm_mma, cudaFuncAttributeMaxDynamicSharedMemorySize, GSMEM);

    const int n4_big = MROWS * DD / 4;   // 786432
    const int n4_w   = DD * DD / 4;      // 147456
    const int bl_big = (n4_big + 255) / 256;
    const int bl_w   = (n4_w + 255) / 256;

    split_bf16<<<bl_big, 256>>>((const float4*)Q, (ushort4*)qh, (ushort4*)ql, n4_big);
    split_bf16<<<bl_big, 256>>>((const float4*)K, (ushort4*)kh, (ushort4*)kl, n4_big);
    split_bf16<<<bl_big, 256>>>((const float4*)V, (ushort4*)vh, (ushort4*)vl, n4_big);
    split_bf16<<<bl_w, 256>>>((const float4*)Wq, (ushort4*)wqh, (ushort4*)wql, n4_w);
    split_bf16<<<bl_w, 256>>>((const float4*)Wk, (ushort4*)wkh, (ushort4*)wkl, n4_w);
    split_bf16<<<bl_w, 256>>>((const float4*)Wv, (ushort4*)wvh, (ushort4*)wvl, n4_w);
    split_bf16<<<bl_w, 256>>>((const float4*)Wo, (ushort4*)woh, (ushort4*)wol, n4_w);

    dim3 gg(DD / BN, MROWS / BM);   // (6, 32)
    gemm_mma<<<gg, 256, GSMEM>>>(qh, ql, wqh, wql, pq);
    gemm_mma<<<gg, 256, GSMEM>>>(kh, kl, wkh, wkl, pk);
    gemm_mma<<<gg, 256, GSMEM>>>(vh, vl, wvh, wvl, pv);

    zero_vsum<<<6, 256>>>();
    vsum_kernel<<<dim3(BB * NH, 8), 256>>>();

    const int n_items = BB * NH * SMID;                 // 49104
    mid_kernel<<<(n_items + 7) / 8, 256>>>(idx);

    global_kernel<<<BB * NH * 2, 256>>>();

    split_bf16<<<bl_big, 256>>>((const float4*)pa, (ushort4*)ah, (ushort4*)al, n4_big);
    gemm_mma<<<gg, 256, GSMEM>>>(ah, al, woh, wol, out);
}

// round 4
// speedup vs baseline: 2.4158x; 1.1890x over previous
#include <cuda_runtime.h>
#include <cuda_bf16.h>
#include <cstdint>
#include <math.h>

// Problem constants
#define BB 2
#define SS 2048
#define DD 768
#define NH 12
#define DK 64
#define DV 64
#define GG 1
#define NIDX 6
#define SMID (SS - 2*GG)          // 2046 middle rows
#define MROWS (BB * SS)           // 4096

// GEMM tiling
#define BM 128
#define BN 128
#define BKK 32                    // bf16 K elems per stage
#define NCHK (DD / BKK)           // 24 k-iterations
#define LDT 40                    // padded row stride (elements): 80B
#define TILEB (128 * LDT * 2)     // 10240 B per tile
#define STAGEB (4 * TILEB)        // Ah, Al, Bh, Bl = 40960 B
#define NSTG 3
#define GSMEM (NSTG * STAGEB)     // 122880 B

// ---------------------------------------------------------------------------
// Scratch (static device globals; runtime allocation is forbidden)
// ---------------------------------------------------------------------------
__device__ float g_q[MROWS * DD];
__device__ float g_k[MROWS * DD];
__device__ float g_v[MROWS * DD];
__device__ float g_vsum[BB * NH * DV];

__device__ __nv_bfloat16 g_qh[MROWS * DD], g_ql[MROWS * DD];
__device__ __nv_bfloat16 g_kh[MROWS * DD], g_kl[MROWS * DD];
__device__ __nv_bfloat16 g_vh[MROWS * DD], g_vl[MROWS * DD];
__device__ __nv_bfloat16 g_ah[MROWS * DD], g_al[MROWS * DD];
__device__ __nv_bfloat16 g_wqh[DD * DD], g_wql[DD * DD];
__device__ __nv_bfloat16 g_wkh[DD * DD], g_wkl[DD * DD];
__device__ __nv_bfloat16 g_wvh[DD * DD], g_wvl[DD * DD];
__device__ __nv_bfloat16 g_woh[DD * DD], g_wol[DD * DD];

// ---------------------------------------------------------------------------
// PTX helpers (portable sm_80+ ISA — compiles under compute_103 family target)
// ---------------------------------------------------------------------------
__device__ __forceinline__ uint32_t smem_u32(const void* p) {
    uint32_t a;
    asm("{ .reg .u64 t; cvta.to.shared.u64 t, %1; cvt.u32.u64 %0, t; }"
        : "=r"(a) : "l"(p));
    return a;
}
__device__ __forceinline__ void cp_async16(uint32_t dst, const void* src) {
    asm volatile("cp.async.cg.shared.global [%0], [%1], 16;"
                 :: "r"(dst), "l"(src) : "memory");
}
__device__ __forceinline__ void cp_commit() {
    asm volatile("cp.async.commit_group;" ::: "memory");
}
template <int N>
__device__ __forceinline__ void cp_wait() {
    asm volatile("cp.async.wait_group %0;" :: "n"(N) : "memory");
}
__device__ __forceinline__ void ldm4(uint32_t* r, uint32_t addr) {
    asm volatile("ldmatrix.sync.aligned.m8n8.x4.shared.b16 {%0,%1,%2,%3}, [%4];"
                 : "=r"(r[0]), "=r"(r[1]), "=r"(r[2]), "=r"(r[3]) : "r"(addr));
}
__device__ __forceinline__ void mma16816(float* c, const uint32_t* a, const uint32_t* b) {
    asm volatile(
        "mma.sync.aligned.m16n8k16.row.col.f32.bf16.bf16.f32 "
        "{%0,%1,%2,%3}, {%4,%5,%6,%7}, {%8,%9}, {%0,%1,%2,%3};"
        : "+f"(c[0]), "+f"(c[1]), "+f"(c[2]), "+f"(c[3])
        : "r"(a[0]), "r"(a[1]), "r"(a[2]), "r"(a[3]), "r"(b[0]), "r"(b[1]));
}

struct GemmArgs {
    const __nv_bfloat16 *Ah, *Al, *Bh, *Bl;
    float* C;
};
struct Gemm3 { GemmArgs g[3]; };

// ---------------------------------------------------------------------------
// C[M,768] = Ah*Bh^T + Ah*Bl^T + Al*Bh^T  (bf16 split-fp32), B is [768,768]
// 128x128 CTA tile, 8 warps (2m x 4n), 64x32 warp tile, BK=32, cp.async x3.
// blockIdx.z selects one of up to 3 independent GEMMs.
// ---------------------------------------------------------------------------
__global__ __launch_bounds__(256, 1) void gemm_mma(Gemm3 ga)
{
    extern __shared__ char smem[];
    const GemmArgs& A = ga.g[blockIdx.z];
    const uint32_t sb = smem_u32(smem);
    const int tid = threadIdx.x;
    const int wid = tid >> 5;
    const int lane = tid & 31;
    const int bm = blockIdx.y * BM;
    const int bn = blockIdx.x * BN;
    const int wm = (wid >> 2) * 64;
    const int wn = (wid & 3) * 32;

    float acc[4][4][4];
    #pragma unroll
    for (int i = 0; i < 4; i++)
        #pragma unroll
        for (int j = 0; j < 4; j++)
            #pragma unroll
            for (int e = 0; e < 4; e++) acc[i][j][e] = 0.0f;

    const __nv_bfloat16* srcs[4] = {A.Ah, A.Al, A.Bh, A.Bl};
    const int rows0[4] = {bm, bm, bn, bn};

    auto issue = [&](int kt, int st) {
        #pragma unroll
        for (int q8 = 0; q8 < 8; q8++) {
            int q = tid + q8 * 256;            // 0..2047
            int t = q >> 9;
            int r = (q >> 2) & 127;
            int c = q & 3;
            const __nv_bfloat16* src = srcs[t] + (size_t)(rows0[t] + r) * DD
                                       + kt * BKK + c * 8;
            uint32_t dst = sb + st * STAGEB + t * TILEB + r * (LDT * 2) + c * 16;
            cp_async16(dst, src);
        }
        cp_commit();
    };

    const int a_row = lane & 15;
    const int a_col = (lane >> 4) * 8;
    const int b_row = (lane & 7) + ((lane >> 4) << 3);
    const int b_col = ((lane >> 3) & 1) * 8;

    auto compute = [&](int st) {
        const uint32_t base = sb + st * STAGEB;
        #pragma unroll
        for (int ks = 0; ks < 2; ks++) {
            const int k0 = ks * 16;
            uint32_t ah[4][4], al[4][4];
            #pragma unroll
            for (int mt = 0; mt < 4; mt++) {
                uint32_t off = (uint32_t)(wm + mt * 16 + a_row) * (LDT * 2)
                             + (k0 + a_col) * 2;
                ldm4(ah[mt], base + off);
                ldm4(al[mt], base + TILEB + off);
            }
            uint32_t bh[2][4], bl[2][4];
            #pragma unroll
            for (int nh = 0; nh < 2; nh++) {
                uint32_t off = (uint32_t)(wn + nh * 16 + b_row) * (LDT * 2)
                             + (k0 + b_col) * 2;
                ldm4(bh[nh], base + 2 * TILEB + off);
                ldm4(bl[nh], base + 3 * TILEB + off);
            }
            #pragma unroll
            for (int mt = 0; mt < 4; mt++)
                #pragma unroll
                for (int j = 0; j < 4; j++) {
                    const uint32_t* bhp = &bh[j >> 1][(j & 1) * 2];
                    const uint32_t* blp = &bl[j >> 1][(j & 1) * 2];
                    mma16816(acc[mt][j], ah[mt], bhp);
                    mma16816(acc[mt][j], ah[mt], blp);
                    mma16816(acc[mt][j], al[mt], bhp);
                }
        }
    };

    issue(0, 0);
    issue(1, 1);
    for (int kt = 0; kt < NCHK; kt++) {
        const int st = kt % NSTG;
        if (kt + 2 < NCHK) {
            issue(kt + 2, (kt + 2) % NSTG);
            cp_wait<2>();
        } else if (kt + 1 < NCHK) {
            cp_wait<1>();
        } else {
            cp_wait<0>();
        }
        __syncthreads();
        compute(st);
        __syncthreads();
    }

    #pragma unroll
    for (int mt = 0; mt < 4; mt++) {
        #pragma unroll
        for (int j = 0; j < 4; j++) {
            int row = bm + wm + mt * 16 + (lane >> 2);
            int col = bn + wn + j * 8 + (lane & 3) * 2;
            *reinterpret_cast<float2*>(A.C + (size_t)row * DD + col)
                = make_float2(acc[mt][j][0], acc[mt][j][1]);
            *reinterpret_cast<float2*>(A.C + (size_t)(row + 8) * DD + col)
                = make_float2(acc[mt][j][2], acc[mt][j][3]);
        }
    }
}

// ---------------------------------------------------------------------------
// fp32 -> (bf16 hi, bf16 lo) split, vectorized x4
// ---------------------------------------------------------------------------
__device__ __forceinline__ void split4(float4 v, ushort4& h, ushort4& l) {
    __nv_bfloat16 b;
    b = __float2bfloat16(v.x); h.x = __bfloat16_as_ushort(b);
    l.x = __bfloat16_as_ushort(__float2bfloat16(v.x - __bfloat162float(b)));
    b = __float2bfloat16(v.y); h.y = __bfloat16_as_ushort(b);
    l.y = __bfloat16_as_ushort(__float2bfloat16(v.y - __bfloat162float(b)));
    b = __float2bfloat16(v.z); h.z = __bfloat16_as_ushort(b);
    l.z = __bfloat16_as_ushort(__float2bfloat16(v.z - __bfloat162float(b)));
    b = __float2bfloat16(v.w); h.w = __bfloat16_as_ushort(b);
    l.w = __bfloat16_as_ushort(__float2bfloat16(v.w - __bfloat162float(b)));
}

__global__ void split_bf16(const float4* __restrict__ x,
                           ushort4* __restrict__ hi, ushort4* __restrict__ lo,
                           int n4)
{
    int i = blockIdx.x * blockDim.x + threadIdx.x;
    if (i >= n4) return;
    ushort4 h, l;
    split4(x[i], h, l);
    hi[i] = h; lo[i] = l;
}

struct SplitW4 {
    const float4* x[4];
    ushort4* hi[4];
    ushort4* lo[4];
};
__global__ void split_w4(SplitW4 a, int n4)
{
    int w = blockIdx.y;
    int i = blockIdx.x * blockDim.x + threadIdx.x;
    if (i >= n4) return;
    ushort4 h, l;
    split4(a.x[w][i], h, l);
    a.hi[w][i] = h; a.lo[w][i] = l;
}

// ---------------------------------------------------------------------------
// Vsum[b,h,dv] = sum_s v[b,s,h*64+dv]
// ---------------------------------------------------------------------------
__global__ void zero_vsum() {
    int i = blockIdx.x * blockDim.x + threadIdx.x;
    if (i < BB * NH * DV) g_vsum[i] = 0.0f;
}

__global__ void vsum_kernel() {
    int bh = blockIdx.x;               // 0..23
    int chunk = blockIdx.y;            // 0..7
    int b = bh / NH, h = bh % NH;
    int dv = threadIdx.x & 63;
    int sub = threadIdx.x >> 6;        // 0..3
    const float* vb = g_v + (size_t)b * SS * DD + h * DV;
    int s0 = chunk * (SS / 8) + sub * (SS / 32);
    float acc = 0.0f;
    for (int s = s0; s < s0 + SS / 32; s++)
        acc += vb[(size_t)s * DD + dv];
    __shared__ float red[256];
    red[threadIdx.x] = acc;
    __syncthreads();
    if (threadIdx.x < DV)
        atomicAdd(&g_vsum[bh * DV + dv],
                  red[dv] + red[64 + dv] + red[128 + dv] + red[192 + dv]);
}

// ---------------------------------------------------------------------------
// Middle rows: out = (Vsum + sum_uniq (e_j-1) v_j) / (S + sum_uniq (e_j-1))
// Writes bf16 hi/lo directly (fused split for the O GEMM).
// ---------------------------------------------------------------------------
__device__ __forceinline__ void store_hl(size_t off, float v) {
    __nv_bfloat16 h = __float2bfloat16(v);
    g_ah[off] = h;
    g_al[off] = __float2bfloat16(v - __bfloat162float(h));
}

__global__ void mid_kernel(const int* __restrict__ idx)
{
    const int warps_per_block = 8;
    int item = blockIdx.x * warps_per_block + (threadIdx.x >> 5);
    const int n_items = BB * NH * SMID;
    if (item >= n_items) return;
    int lane = threadIdx.x & 31;

    int i = item % SMID;
    int h = (item / SMID) % NH;
    int b = item / (SMID * NH);
    int s = i + GG;

    const float* qrow = g_q + ((size_t)b * SS + s) * DD + h * DK;
    float q0 = qrow[lane];
    float q1 = qrow[lane + 32];

    int cols[NIDX];
    #pragma unroll
    for (int j = 0; j < NIDX; j++) cols[j] = idx[i * NIDX + j];

    float sc[NIDX];
    #pragma unroll
    for (int j = 0; j < NIDX; j++) {
        const float* krow = g_k + ((size_t)b * SS + cols[j]) * DD + h * DK;
        float p = q0 * krow[lane] + q1 * krow[lane + 32];
        #pragma unroll
        for (int o = 16; o > 0; o >>= 1) p += __shfl_xor_sync(0xFFFFFFFFu, p, o);
        sc[j] = p;
    }

    float wgt[NIDX];
    float denom = (float)SS;
    #pragma unroll
    for (int j = 0; j < NIDX; j++) {
        bool dup = false;
        #pragma unroll
        for (int jj = 0; jj < NIDX; jj++)
            if (jj < j) dup = dup || (cols[jj] == cols[j]);
        float w = dup ? 0.0f : (expf(sc[j] * 0.125f) - 1.0f);
        wgt[j] = w;
        denom += w;
    }

    const float* vs = g_vsum + (b * NH + h) * DV;
    float o0 = vs[lane];
    float o1 = vs[lane + 32];
    #pragma unroll
    for (int j = 0; j < NIDX; j++) {
        const float* vrow = g_v + ((size_t)b * SS + cols[j]) * DD + h * DV;
        o0 = fmaf(wgt[j], vrow[lane], o0);
        o1 = fmaf(wgt[j], vrow[lane + 32], o1);
    }
    float inv = 1.0f / denom;
    size_t base = ((size_t)b * SS + s) * DD + h * DV;
    store_hl(base + lane, o0 * inv);
    store_hl(base + lane + 32, o1 * inv);
}

// ---------------------------------------------------------------------------
// Global rows (s=0, s=2047): full softmax over all 2048 keys.
// ---------------------------------------------------------------------------
__global__ void global_kernel()
{
    int item = blockIdx.x;
    int r = item % 2;
    int h = (item / 2) % NH;
    int b = item / (2 * NH);
    int s = r ? (SS - 1) : 0;
    int tid = threadIdx.x;

    __shared__ float sc[SS];
    __shared__ float qs[DK];
    __shared__ float red[256];

    const float* qrow = g_q + ((size_t)b * SS + s) * DD + h * DK;
    if (tid < DK) qs[tid] = qrow[tid];
    __syncthreads();

    for (int t = tid; t < SS; t += 256) {
        const float* krow = g_k + ((size_t)b * SS + t) * DD + h * DK;
        float p = 0.0f;
        #pragma unroll
        for (int d = 0; d < DK; d++) p = fmaf(qs[d], krow[d], p);
        sc[t] = p * 0.125f;
    }
    __syncthreads();

    float m = -1e30f;
    for (int t = tid; t < SS; t += 256) m = fmaxf(m, sc[t]);
    red[tid] = m; __syncthreads();
    for (int o = 128; o > 0; o >>= 1) {
        if (tid < o) red[tid] = fmaxf(red[tid], red[tid + o]);
        __syncthreads();
    }
    m = red[0];
    __syncthreads();

    float sum = 0.0f;
    for (int t = tid; t < SS; t += 256) {
        float e = expf(sc[t] - m);
        sc[t] = e;
        sum += e;
    }
    red[tid] = sum; __syncthreads();
    for (int o = 128; o > 0; o >>= 1) {
        if (tid < o) red[tid] += red[tid + o];
        __syncthreads();
    }
    float inv = 1.0f / red[0];
    __syncthreads();

    int dv = tid % DV;
    int chunk = tid / DV;
    float acc = 0.0f;
    const float* vb = g_v + (size_t)b * SS * DD + h * DV + dv;
    for (int t = chunk * (SS / 4); t < (chunk + 1) * (SS / 4); t++)
        acc = fmaf(sc[t], vb[(size_t)t * DD], acc);
    red[tid] = acc; __syncthreads();
    if (tid < DV) {
        float o = (red[dv] + red[DV + dv] + red[2 * DV + dv] + red[3 * DV + dv]) * inv;
        store_hl(((size_t)b * SS + s) * DD + h * DV + dv, o);
    }
}

// ---------------------------------------------------------------------------
extern "C" void kernel_launch(void* const* d_in, const int* in_sizes, int n_in,
                              void* d_out, int out_size)
{
    const float* Q  = (const float*)d_in[0];
    const float* K  = (const float*)d_in[1];
    const float* V  = (const float*)d_in[2];
    const float* Wq = (const float*)d_in[3];
    const float* Wk = (const float*)d_in[4];
    const float* Wv = (const float*)d_in[5];
    const float* Wo = (const float*)d_in[6];
    const int*   idx = (const int*)d_in[7];
    float* out = (float*)d_out;

    float *pq, *pk, *pv;
    cudaGetSymbolAddress((void**)&pq, g_q);
    cudaGetSymbolAddress((void**)&pk, g_k);
    cudaGetSymbolAddress((void**)&pv, g_v);

    __nv_bfloat16 *qh, *ql, *kh, *kl, *vh, *vl, *ah, *al;
    __nv_bfloat16 *wqh, *wql, *wkh, *wkl, *wvh, *wvl, *woh, *wol;
    cudaGetSymbolAddress((void**)&qh, g_qh);  cudaGetSymbolAddress((void**)&ql, g_ql);
    cudaGetSymbolAddress((void**)&kh, g_kh);  cudaGetSymbolAddress((void**)&kl, g_kl);
    cudaGetSymbolAddress((void**)&vh, g_vh);  cudaGetSymbolAddress((void**)&vl, g_vl);
    cudaGetSymbolAddress((void**)&ah, g_ah);  cudaGetSymbolAddress((void**)&al, g_al);
    cudaGetSymbolAddress((void**)&wqh, g_wqh); cudaGetSymbolAddress((void**)&wql, g_wql);
    cudaGetSymbolAddress((void**)&wkh, g_wkh); cudaGetSymbolAddress((void**)&wkl, g_wkl);
    cudaGetSymbolAddress((void**)&wvh, g_wvh); cudaGetSymbolAddress((void**)&wvl, g_wvl);
    cudaGetSymbolAddress((void**)&woh, g_woh); cudaGetSymbolAddress((void**)&wol, g_wol);

    cudaFuncSetAttribute(gemm_mma, cudaFuncAttributeMaxDynamicSharedMemorySize, GSMEM);

    const int n4_big = MROWS * DD / 4;
    const int n4_w   = DD * DD / 4;
    const int bl_big = (n4_big + 255) / 256;
    const int bl_w   = (n4_w + 255) / 256;

    // Launch order matters for ncu (-s 5 -c 1 captures launch #6 = gemm_mma).
    zero_vsum<<<6, 256>>>();                                                   // 1
    split_bf16<<<bl_big, 256>>>((const float4*)Q, (ushort4*)qh, (ushort4*)ql, n4_big); // 2
    split_bf16<<<bl_big, 256>>>((const float4*)K, (ushort4*)kh, (ushort4*)kl, n4_big); // 3
    split_bf16<<<bl_big, 256>>>((const float4*)V, (ushort4*)vh, (ushort4*)vl, n4_big); // 4

    SplitW4 sw;
    sw.x[0] = (const float4*)Wq; sw.hi[0] = (ushort4*)wqh; sw.lo[0] = (ushort4*)wql;
    sw.x[1] = (const float4*)Wk; sw.hi[1] = (ushort4*)wkh; sw.lo[1] = (ushort4*)wkl;
    sw.x[2] = (const float4*)Wv; sw.hi[2] = (ushort4*)wvh; sw.lo[2] = (ushort4*)wvl;
    sw.x[3] = (const float4*)Wo; sw.hi[3] = (ushort4*)woh; sw.lo[3] = (ushort4*)wol;
    split_w4<<<dim3(bl_w, 4), 256>>>(sw, n4_w);                                // 5

    Gemm3 g3;
    g3.g[0] = {qh, ql, wqh, wql, pq};
    g3.g[1] = {kh, kl, wkh, wkl, pk};
    g3.g[2] = {vh, vl, wvh, wvl, pv};
    gemm_mma<<<dim3(DD / BN, MROWS / BM, 3), 256, GSMEM>>>(g3);                // 6  <- profiled

    vsum_kernel<<<dim3(BB * NH, 8), 256>>>();                                  // 7
    const int n_items = BB * NH * SMID;
    mid_kernel<<<(n_items + 7) / 8, 256>>>(idx);                               // 8
    global_kernel<<<BB * NH * 2, 256>>>();                                     // 9

    Gemm3 go;
    go.g[0] = {ah, al, woh, wol, out};
    go.g[1] = go.g[0];
    go.g[2] = go.g[0];
    gemm_mma<<<dim3(DD / BN, MROWS / BM, 1), 256, GSMEM>>>(go);                // 10
}